// round 15
// baseline (speedup 1.0000x reference)
#include <cuda_runtime.h>
#include <math.h>

// z[b] = sum_t x[b,t]*K[t] + z0 + e
// K[t] = sum_h w_h*b_h*a_h^(T-1-t),  z0 = sum_h w_h*c_h*(1-a_h^T)/(1-a_h)
#define TLEN 4096
#define HDIM 512
#define BATCH 64
#define CHUNK 16
#define NCHUNK (TLEN / CHUNK)   // 256 blocks

// Scratch (__device__ globals; no allocations allowed)
__device__ __align__(16) float g_K[TLEN];
__device__ float g_z0;

// Kernel 1 (primary): K chunk of 16 t's per block, seed via log2f/exp2f.
// launch_dependents at the TOP: dependent grid rolls out + issues its x loads
// concurrently with this kernel's body. Data-readiness is carried by the
// dependent's griddepcontrol.wait (= wait for primary grid completion).
__global__ __launch_bounds__(HDIM) void build_K_kernel(
    const float* __restrict__ a, const float* __restrict__ b,
    const float* __restrict__ c, const float* __restrict__ w)
{
    asm volatile("griddepcontrol.launch_dependents;");

    __shared__ float part[CHUNK][HDIM];   // 32 KB
    __shared__ float zp[16];
    const int h = threadIdx.x;
    const int j = blockIdx.x;             // exponents s in [16j, 16j+16)
    const int warp = h >> 5, lane = h & 31;

    // issue all LDGs up front so they overlap the MUFU chain
    const float af = a[h];
    const float bf = b[h];
    const float wf = w[h];

    const float l2a = log2f(af);          // relative-accurate (NOT __log2f)
    float p = (wf * bf) * exp2f((float)(j * CHUNK) * l2a);

    #pragma unroll
    for (int i = 0; i < CHUNK; i++) { part[i][h] = p; p *= af; }

    if (j == 0) {                          // z0 = sum_h w*c*(1-a^T)/(1-a)
        const float aT  = exp2f((float)TLEN * l2a);
        const float geo = (1.0f - aT) / (1.0f - af);
        float term = wf * c[h] * geo;
        #pragma unroll
        for (int off = 16; off; off >>= 1)
            term += __shfl_down_sync(0xffffffffu, term, off);
        if (lane == 0) zp[warp] = term;
    }
    __syncthreads();

    // warp i reduces the h-dimension for t-offset i
    float s = 0.0f;
    #pragma unroll
    for (int k = 0; k < HDIM / 32; k++) s += part[warp][lane + 32 * k];
    #pragma unroll
    for (int off = 16; off; off >>= 1) s += __shfl_down_sync(0xffffffffu, s, off);
    if (lane == 0) g_K[TLEN - 1 - (j * CHUNK + warp)] = s;

    if (j == 0 && h == 0) {
        float sz = 0.0f;
        #pragma unroll
        for (int i = 0; i < 16; i++) sz += zp[i];
        g_z0 = sz;
    }
}

// Kernel 2 (PDL secondary): one block per batch row, 1024 threads.
// Order: x loads FIRST (overlap primary), then wait (primary completion),
// then K/z0 loads from L2.
__global__ __launch_bounds__(1024) void dot_kernel(
    const float* __restrict__ x, const float* __restrict__ e,
    float* __restrict__ out)
{
    const int row = blockIdx.x;
    const int tid = threadIdx.x;

    // independent prologue: overlaps the primary grid's body
    const float4 xv = ((const float4*)(x + (size_t)row * TLEN))[tid];
    const float ev = e[0];

    // block until the primary grid (build_K) has completed; its stores visible
    asm volatile("griddepcontrol.wait;" ::: "memory");

    const float4 kv = __ldcg(&((const float4*)g_K)[tid]);
    const float z0 = __ldcg(&g_z0);

    float s = xv.x * kv.x + xv.y * kv.y + xv.z * kv.z + xv.w * kv.w;
    if (tid == 0) s += z0 + ev;           // fold z0+e into warp0/lane0 partial
    #pragma unroll
    for (int off = 16; off; off >>= 1) s += __shfl_down_sync(0xffffffffu, s, off);

    __shared__ float sp[32];
    const int warp = tid >> 5, lane = tid & 31;
    if (lane == 0) sp[warp] = s;
    __syncthreads();

    if (warp == 0) {
        float t = sp[lane];
        #pragma unroll
        for (int off = 16; off; off >>= 1) t += __shfl_down_sync(0xffffffffu, t, off);
        if (lane == 0) out[row] = t;
    }
}

extern "C" void kernel_launch(void* const* d_in, const int* in_sizes, int n_in,
                              void* d_out, int out_size)
{
    const float* x = (const float*)d_in[0];   // [B, T]
    const float* a = (const float*)d_in[1];   // [H]
    const float* b = (const float*)d_in[2];   // [H]
    const float* c = (const float*)d_in[3];   // [H]
    const float* w = (const float*)d_in[4];   // [H]
    const float* e = (const float*)d_in[5];   // [1]
    float* out = (float*)d_out;               // [B]

    build_K_kernel<<<NCHUNK, HDIM>>>(a, b, c, w);

    // dot as programmatic dependent of build_K (PDL edge; graph-capturable)
    cudaLaunchAttribute attrs[1];
    attrs[0].id = cudaLaunchAttributeProgrammaticStreamSerialization;
    attrs[0].val.programmaticStreamSerializationAllowed = 1;
    cudaLaunchConfig_t cfg = {};
    cfg.gridDim  = dim3(BATCH);
    cfg.blockDim = dim3(1024);
    cfg.dynamicSmemBytes = 0;
    cfg.stream = 0;
    cfg.attrs = attrs;
    cfg.numAttrs = 1;
    cudaLaunchKernelEx(&cfg, dot_kernel, x, e, out);
}

// round 16
// speedup vs baseline: 1.0265x; 1.0265x over previous
#include <cuda_runtime.h>
#include <math.h>

// z[b] = sum_t x[b,t]*K[t] + z0 + e
// K[t] = sum_h w_h*b_h*a_h^(T-1-t),  z0 = sum_h w_h*c_h*(1-a_h^T)/(1-a_h)
#define TLEN 4096
#define HDIM 512
#define BATCH 64
#define CHUNK 16
#define NCHUNK (TLEN / CHUNK)   // 256 blocks
#define DTHR 128                // dot threads per block
#define DVEC 8                  // float4 loads per dot thread

// Scratch (__device__ globals; no allocations allowed)
__device__ __align__(16) float g_K[TLEN];
__device__ float g_z0;

// Kernel 1: identical to the proven R12 build_K (7.62us config).
__global__ __launch_bounds__(HDIM) void build_K_kernel(
    const float* __restrict__ a, const float* __restrict__ b,
    const float* __restrict__ c, const float* __restrict__ w)
{
    __shared__ float part[CHUNK][HDIM];   // 32 KB
    __shared__ float zp[16];
    const int h = threadIdx.x;
    const int j = blockIdx.x;             // exponents s in [16j, 16j+16)
    const int warp = h >> 5, lane = h & 31;

    // issue all LDGs up front so they overlap the MUFU chain
    const float af = a[h];
    const float bf = b[h];
    const float wf = w[h];

    const float l2a = log2f(af);          // relative-accurate (NOT __log2f)
    float p = (wf * bf) * exp2f((float)(j * CHUNK) * l2a);

    #pragma unroll
    for (int i = 0; i < CHUNK; i++) { part[i][h] = p; p *= af; }

    if (j == 0) {                          // z0 = sum_h w*c*(1-a^T)/(1-a)
        const float aT  = exp2f((float)TLEN * l2a);
        const float geo = (1.0f - aT) / (1.0f - af);
        float term = wf * c[h] * geo;
        #pragma unroll
        for (int off = 16; off; off >>= 1)
            term += __shfl_down_sync(0xffffffffu, term, off);
        if (lane == 0) zp[warp] = term;
    }
    __syncthreads();

    // warp i reduces the h-dimension for t-offset i
    float s = 0.0f;
    #pragma unroll
    for (int k = 0; k < HDIM / 32; k++) s += part[warp][lane + 32 * k];
    #pragma unroll
    for (int off = 16; off; off >>= 1) s += __shfl_down_sync(0xffffffffu, s, off);
    if (lane == 0) g_K[TLEN - 1 - (j * CHUNK + warp)] = s;

    if (j == 0 && h == 0) {
        float sz = 0.0f;
        #pragma unroll
        for (int i = 0; i < 16; i++) sz += zp[i];
        g_z0 = sz;
    }

    // all K/z0 stores issued -> release the dependent grid
    asm volatile("griddepcontrol.launch_dependents;");
}

// Kernel 2 (PDL secondary): one block per row, 128 threads, 8 float4 each.
// All 1024 float4 loads per block issued up-front (full latency overlap);
// short 4-warp reduce tail.
__global__ __launch_bounds__(DTHR) void dot_kernel(
    const float* __restrict__ x, const float* __restrict__ e,
    float* __restrict__ out)
{
    const int row = blockIdx.x;
    const int tid = threadIdx.x;

    const float4* xr = (const float4*)(x + (size_t)row * TLEN);
    const float ev = e[0];

    // issue all x loads first (independent)
    float4 xv[DVEC];
    #pragma unroll
    for (int k = 0; k < DVEC; k++) xv[k] = xr[tid + DTHR * k];

    asm volatile("griddepcontrol.wait;" ::: "memory");

    const float4* kr = (const float4*)g_K;
    float4 kv[DVEC];
    #pragma unroll
    for (int k = 0; k < DVEC; k++) kv[k] = __ldcg(&kr[tid + DTHR * k]);
    const float z0 = __ldcg(&g_z0);

    // two independent accumulators to halve the FMA dependency chain
    float s0 = 0.0f, s1 = 0.0f;
    #pragma unroll
    for (int k = 0; k < DVEC; k += 2) {
        s0 += xv[k].x * kv[k].x + xv[k].y * kv[k].y
            + xv[k].z * kv[k].z + xv[k].w * kv[k].w;
        s1 += xv[k+1].x * kv[k+1].x + xv[k+1].y * kv[k+1].y
            + xv[k+1].z * kv[k+1].z + xv[k+1].w * kv[k+1].w;
    }
    float s = s0 + s1;
    #pragma unroll
    for (int off = 16; off; off >>= 1) s += __shfl_down_sync(0xffffffffu, s, off);

    __shared__ float sp[4];
    const int warp = tid >> 5, lane = tid & 31;
    if (lane == 0) sp[warp] = s;
    __syncthreads();

    if (warp == 0) {
        float t = (lane < 4) ? sp[lane] : 0.0f;
        t += __shfl_down_sync(0xffffffffu, t, 2);
        t += __shfl_down_sync(0xffffffffu, t, 1);
        if (lane == 0) out[row] = t + z0 + ev;
    }
}

extern "C" void kernel_launch(void* const* d_in, const int* in_sizes, int n_in,
                              void* d_out, int out_size)
{
    const float* x = (const float*)d_in[0];   // [B, T]
    const float* a = (const float*)d_in[1];   // [H]
    const float* b = (const float*)d_in[2];   // [H]
    const float* c = (const float*)d_in[3];   // [H]
    const float* w = (const float*)d_in[4];   // [H]
    const float* e = (const float*)d_in[5];   // [1]
    float* out = (float*)d_out;               // [B]

    build_K_kernel<<<NCHUNK, HDIM>>>(a, b, c, w);

    // dot as programmatic dependent of build_K (PDL edge; graph-capturable)
    cudaLaunchAttribute attrs[1];
    attrs[0].id = cudaLaunchAttributeProgrammaticStreamSerialization;
    attrs[0].val.programmaticStreamSerializationAllowed = 1;
    cudaLaunchConfig_t cfg = {};
    cfg.gridDim  = dim3(BATCH);
    cfg.blockDim = dim3(DTHR);
    cfg.dynamicSmemBytes = 0;
    cfg.stream = 0;
    cfg.attrs = attrs;
    cfg.numAttrs = 1;
    cudaLaunchKernelEx(&cfg, dot_kernel, x, e, out);
}